// round 1
// baseline (speedup 1.0000x reference)
#include <cuda_runtime.h>
#include <math.h>

// ------------------------------------------------------------------
// Problem constants: B=8, M=1024, C=768
// ------------------------------------------------------------------
#define BATCH 8
#define SEQ   1024
#define CH    768

// Scratch (device globals; allocation-free per harness rules)
__device__ __align__(16) float g_qkv   [BATCH * SEQ * (3 * CH)]; // 75.5 MB
__device__ __align__(16) float g_scores[BATCH * SEQ * SEQ];      // 33.5 MB
__device__ __align__(16) float g_lo    [BATCH * SEQ * CH];       // layout_o
__device__ __align__(16) float g_cq    [BATCH * SEQ * CH];
__device__ __align__(16) float g_kv    [BATCH * SEQ * (2 * CH)]; // 50 MB
__device__ __align__(16) float g_merge [BATCH * SEQ * CH];

// ------------------------------------------------------------------
// Tiled SGEMM: 128x128x16 block tile, 8x8 per-thread micro-tile,
// 256 threads. All dims assumed multiples of 128 (M,N) / 16 (K).
// ------------------------------------------------------------------
#define BM 128
#define BN 128
#define BK 16
#define TM 8
#define TN 8
#define PAD 4

// NN: C[m,n] = sum_k A[m,k]*B[k,n] (+ bias[n]); batched via blockIdx.z
__global__ void __launch_bounds__(256, 2) sgemm_nn(
    const float* __restrict__ A, int lda, long long strideA,
    const float* __restrict__ B, int ldb, long long strideB,
    const float* __restrict__ bias,
    float* __restrict__ C, int ldc, long long strideC,
    int K)
{
    const int b = blockIdx.z;
    A += (size_t)b * strideA;
    B += (size_t)b * strideB;
    C += (size_t)b * strideC;

    __shared__ float As[BK][BM + PAD];
    __shared__ float Bs[BK][BN + PAD];

    const int tid = threadIdx.x;
    const int m0 = blockIdx.y * BM;
    const int n0 = blockIdx.x * BN;

    // A tile load mapping: 128 rows x 16 k = 512 float4, 2 per thread
    const int a_row = tid >> 2;            // 0..63
    const int a_k   = (tid & 3) << 2;      // 0,4,8,12
    // B tile load mapping: 16 k x 128 n = 512 float4, 2 per thread
    const int b_k = tid >> 5;              // 0..7
    const int b_n = (tid & 31) << 2;       // 0..124

    const int ty = tid >> 4, tx = tid & 15;

    float acc[TM][TN];
    #pragma unroll
    for (int i = 0; i < TM; i++)
        #pragma unroll
        for (int j = 0; j < TN; j++) acc[i][j] = 0.f;

    const float* Aptr = A + (size_t)m0 * lda;
    const float* Bptr = B + n0;

    for (int k0 = 0; k0 < K; k0 += BK) {
        #pragma unroll
        for (int i = 0; i < 2; i++) {
            const int m = a_row + i * 64;
            float4 v = *(const float4*)(Aptr + (size_t)m * lda + k0 + a_k);
            As[a_k + 0][m] = v.x;
            As[a_k + 1][m] = v.y;
            As[a_k + 2][m] = v.z;
            As[a_k + 3][m] = v.w;
        }
        #pragma unroll
        for (int i = 0; i < 2; i++) {
            const int k = b_k + i * 8;
            float4 v = *(const float4*)(Bptr + (size_t)(k0 + k) * ldb + b_n);
            *(float4*)&Bs[k][b_n] = v;
        }
        __syncthreads();

        #pragma unroll
        for (int kk = 0; kk < BK; kk++) {
            float4 a0 = *(const float4*)&As[kk][ty * TM];
            float4 a1 = *(const float4*)&As[kk][ty * TM + 4];
            float4 b0 = *(const float4*)&Bs[kk][tx * TN];
            float4 b1 = *(const float4*)&Bs[kk][tx * TN + 4];
            float af[TM] = {a0.x, a0.y, a0.z, a0.w, a1.x, a1.y, a1.z, a1.w};
            float bf[TN] = {b0.x, b0.y, b0.z, b0.w, b1.x, b1.y, b1.z, b1.w};
            #pragma unroll
            for (int i = 0; i < TM; i++)
                #pragma unroll
                for (int j = 0; j < TN; j++)
                    acc[i][j] += af[i] * bf[j];
        }
        __syncthreads();
    }

    #pragma unroll
    for (int i = 0; i < TM; i++) {
        const int m = m0 + ty * TM + i;
        #pragma unroll
        for (int j = 0; j < TN; j += 4) {
            const int n = n0 + tx * TN + j;
            float4 v;
            v.x = acc[i][j + 0];
            v.y = acc[i][j + 1];
            v.z = acc[i][j + 2];
            v.w = acc[i][j + 3];
            if (bias) {
                v.x += bias[n + 0];
                v.y += bias[n + 1];
                v.z += bias[n + 2];
                v.w += bias[n + 3];
            }
            *(float4*)(C + (size_t)m * ldc + n) = v;
        }
    }
}

// NT with masked-score epilogue:
// S[m,n] = valid(m,n) ? scale * sum_d A[m,d]*B[n,d] : -10000
__global__ void __launch_bounds__(256, 2) sgemm_nt_mask(
    const float* __restrict__ A, int lda, long long strideA,
    const float* __restrict__ B, int ldb, long long strideB,
    const float* __restrict__ mask,   // [BATCH, SEQ]
    float scale,
    float* __restrict__ C, int ldc, long long strideC,
    int K)
{
    const int b = blockIdx.z;
    A += (size_t)b * strideA;
    B += (size_t)b * strideB;
    C += (size_t)b * strideC;
    const float* mrow = mask + (size_t)b * SEQ;

    __shared__ float As[BK][BM + PAD];
    __shared__ float Bs[BK][BN + PAD];

    const int tid = threadIdx.x;
    const int m0 = blockIdx.y * BM;
    const int n0 = blockIdx.x * BN;

    const int l_row = tid >> 2;            // 0..63
    const int l_k   = (tid & 3) << 2;      // 0,4,8,12
    const int ty = tid >> 4, tx = tid & 15;

    float acc[TM][TN];
    #pragma unroll
    for (int i = 0; i < TM; i++)
        #pragma unroll
        for (int j = 0; j < TN; j++) acc[i][j] = 0.f;

    const float* Aptr = A + (size_t)m0 * lda;
    const float* Bptr = B + (size_t)n0 * ldb;

    for (int k0 = 0; k0 < K; k0 += BK) {
        #pragma unroll
        for (int i = 0; i < 2; i++) {
            const int m = l_row + i * 64;
            float4 v = *(const float4*)(Aptr + (size_t)m * lda + k0 + l_k);
            As[l_k + 0][m] = v.x;
            As[l_k + 1][m] = v.y;
            As[l_k + 2][m] = v.z;
            As[l_k + 3][m] = v.w;
        }
        #pragma unroll
        for (int i = 0; i < 2; i++) {
            const int n = l_row + i * 64;
            float4 v = *(const float4*)(Bptr + (size_t)n * ldb + k0 + l_k);
            Bs[l_k + 0][n] = v.x;
            Bs[l_k + 1][n] = v.y;
            Bs[l_k + 2][n] = v.z;
            Bs[l_k + 3][n] = v.w;
        }
        __syncthreads();

        #pragma unroll
        for (int kk = 0; kk < BK; kk++) {
            float4 a0 = *(const float4*)&As[kk][ty * TM];
            float4 a1 = *(const float4*)&As[kk][ty * TM + 4];
            float4 b0 = *(const float4*)&Bs[kk][tx * TN];
            float4 b1 = *(const float4*)&Bs[kk][tx * TN + 4];
            float af[TM] = {a0.x, a0.y, a0.z, a0.w, a1.x, a1.y, a1.z, a1.w};
            float bf[TN] = {b0.x, b0.y, b0.z, b0.w, b1.x, b1.y, b1.z, b1.w};
            #pragma unroll
            for (int i = 0; i < TM; i++)
                #pragma unroll
                for (int j = 0; j < TN; j++)
                    acc[i][j] += af[i] * bf[j];
        }
        __syncthreads();
    }

    float mm[TM], mn[TN];
    #pragma unroll
    for (int i = 0; i < TM; i++) mm[i] = mrow[m0 + ty * TM + i];
    #pragma unroll
    for (int j = 0; j < TN; j++) mn[j] = mrow[n0 + tx * TN + j];

    #pragma unroll
    for (int i = 0; i < TM; i++) {
        const int m = m0 + ty * TM + i;
        #pragma unroll
        for (int j = 0; j < TN; j += 4) {
            const int n = n0 + tx * TN + j;
            float4 v;
            v.x = (mm[i] != 0.f && mn[j + 0] != 0.f) ? acc[i][j + 0] * scale : -10000.f;
            v.y = (mm[i] != 0.f && mn[j + 1] != 0.f) ? acc[i][j + 1] * scale : -10000.f;
            v.z = (mm[i] != 0.f && mn[j + 2] != 0.f) ? acc[i][j + 2] * scale : -10000.f;
            v.w = (mm[i] != 0.f && mn[j + 3] != 0.f) ? acc[i][j + 3] * scale : -10000.f;
            *(float4*)(C + (size_t)m * ldc + n) = v;
        }
    }
}

// Row softmax over N=1024 (in place), one block per row, 256 threads.
__global__ void __launch_bounds__(256) softmax_rows(float* __restrict__ S)
{
    const long long row = blockIdx.x;
    float* p = S + row * (long long)SEQ;
    const int tid = threadIdx.x;

    __shared__ float red[256];

    float lmax = -INFINITY;
    #pragma unroll
    for (int i = tid; i < SEQ; i += 256) lmax = fmaxf(lmax, p[i]);
    red[tid] = lmax;
    __syncthreads();
    for (int s = 128; s > 0; s >>= 1) {
        if (tid < s) red[tid] = fmaxf(red[tid], red[tid + s]);
        __syncthreads();
    }
    const float rmax = red[0];
    __syncthreads();

    float lsum = 0.f;
    #pragma unroll
    for (int i = tid; i < SEQ; i += 256) {
        float e = __expf(p[i] - rmax);
        p[i] = e;
        lsum += e;
    }
    red[tid] = lsum;
    __syncthreads();
    for (int s = 128; s > 0; s >>= 1) {
        if (tid < s) red[tid] += red[tid + s];
        __syncthreads();
    }
    const float inv = 1.0f / red[0];
    __syncthreads();

    #pragma unroll
    for (int i = tid; i < SEQ; i += 256) p[i] *= inv;
}

// ------------------------------------------------------------------
// Launch
// ------------------------------------------------------------------
extern "C" void kernel_launch(void* const* d_in, const int* in_sizes, int n_in,
                              void* d_out, int out_size)
{
    (void)in_sizes; (void)n_in; (void)out_size;

    const float* layout_x = (const float*)d_in[0];  // [8,1024,768]
    const float* text_x   = (const float*)d_in[1];  // [8,1024,768]
    const float* mask     = (const float*)d_in[2];  // [8,1024]
    const float* Wqkv     = (const float*)d_in[3];  // [768,2304]
    const float* bqkv     = (const float*)d_in[4];  // [2304]
    const float* Wq       = (const float*)d_in[5];  // [768,768]
    const float* bq       = (const float*)d_in[6];
    const float* Wkv      = (const float*)d_in[7];  // [768,1536]
    const float* bkv      = (const float*)d_in[8];
    const float* Wffn     = (const float*)d_in[9];  // [768,768]
    const float* bffn     = (const float*)d_in[10];
    float* out = (float*)d_out;                     // [8,1024,768]

    float *qkv, *scores, *lo, *cq, *kv, *merge;
    cudaGetSymbolAddress((void**)&qkv,    g_qkv);
    cudaGetSymbolAddress((void**)&scores, g_scores);
    cudaGetSymbolAddress((void**)&lo,     g_lo);
    cudaGetSymbolAddress((void**)&cq,     g_cq);
    cudaGetSymbolAddress((void**)&kv,     g_kv);
    cudaGetSymbolAddress((void**)&merge,  g_merge);

    const float scale = rsqrtf((float)CH);
    const dim3 blk(256);
    const long long sQKV = (long long)SEQ * 3 * CH;   // per-batch qkv stride
    const long long sS   = (long long)SEQ * SEQ;
    const long long sC   = (long long)SEQ * CH;
    const long long sKV  = (long long)SEQ * 2 * CH;

    // 1) qkv = layout_x @ Wqkv + bqkv   [8192 x 2304 x 768]
    sgemm_nn<<<dim3(3 * CH / BN, BATCH * SEQ / BM, 1), blk>>>(
        layout_x, CH, 0, Wqkv, 3 * CH, 0, bqkv, qkv, 3 * CH, 0, CH);

    // 2) scores = mask(Q @ K^T * scale)   per-batch [1024 x 1024 x 768]
    sgemm_nt_mask<<<dim3(SEQ / BN, SEQ / BM, BATCH), blk>>>(
        qkv + 0, 3 * CH, sQKV, qkv + CH, 3 * CH, sQKV, mask, scale,
        scores, SEQ, sS, CH);

    // 3) softmax rows
    softmax_rows<<<BATCH * SEQ, blk>>>(scores);

    // 4) layout_o = P @ V   per-batch [1024 x 768 x 1024]
    sgemm_nn<<<dim3(CH / BN, SEQ / BM, BATCH), blk>>>(
        scores, SEQ, sS, qkv + 2 * CH, 3 * CH, sQKV, nullptr,
        lo, CH, sC, SEQ);

    // 5) cq = layout_o @ Wq + bq   [8192 x 768 x 768]
    sgemm_nn<<<dim3(CH / BN, BATCH * SEQ / BM, 1), blk>>>(
        lo, CH, 0, Wq, CH, 0, bq, cq, CH, 0, CH);

    // 6) kv = text_x @ Wkv + bkv   [8192 x 1536 x 768]
    sgemm_nn<<<dim3(2 * CH / BN, BATCH * SEQ / BM, 1), blk>>>(
        text_x, CH, 0, Wkv, 2 * CH, 0, bkv, kv, 2 * CH, 0, CH);

    // 7) scores = mask(CQ @ CK^T * scale)   per-batch
    sgemm_nt_mask<<<dim3(SEQ / BN, SEQ / BM, BATCH), blk>>>(
        cq, CH, sC, kv + 0, 2 * CH, sKV, mask, scale,
        scores, SEQ, sS, CH);

    // 8) softmax rows
    softmax_rows<<<BATCH * SEQ, blk>>>(scores);

    // 9) merge = P @ CV   per-batch [1024 x 768 x 1024]
    sgemm_nn<<<dim3(CH / BN, SEQ / BM, BATCH), blk>>>(
        scores, SEQ, sS, kv + CH, 2 * CH, sKV, nullptr,
        merge, CH, sC, SEQ);

    // 10) out = merge @ Wffn + bffn   [8192 x 768 x 768]
    sgemm_nn<<<dim3(CH / BN, BATCH * SEQ / BM, 1), blk>>>(
        merge, CH, 0, Wffn, CH, 0, bffn, out, CH, 0, CH);
}

// round 2
// speedup vs baseline: 2.1817x; 2.1817x over previous
#include <cuda_runtime.h>
#include <math.h>
#include <stdint.h>

// ------------------------------------------------------------------
// Problem constants: B=8, M=1024, C=768
// ------------------------------------------------------------------
#define BATCH 8
#define SEQ   1024
#define CH    768

// Scratch (device globals; allocation-free per harness rules)
__device__ __align__(16) float g_qkv   [BATCH * SEQ * (3 * CH)];
__device__ __align__(16) float g_scores[BATCH * SEQ * SEQ];
__device__ __align__(16) float g_lo    [BATCH * SEQ * CH];
__device__ __align__(16) float g_cq    [BATCH * SEQ * CH];
__device__ __align__(16) float g_kv    [BATCH * SEQ * (2 * CH)];
__device__ __align__(16) float g_merge [BATCH * SEQ * CH];

#define BM 128
#define BN 128
#define BK 16

// ------------------------------------------------------------------
// TF32 helpers
// ------------------------------------------------------------------
__device__ __forceinline__ unsigned f2tf32(float x) {
    unsigned u;
    asm("cvt.rna.tf32.f32 %0, %1;" : "=r"(u) : "f"(x));
    return u;
}

__device__ __forceinline__ void mma_tf32(float* d, const unsigned* a, const unsigned* b) {
    asm volatile(
        "mma.sync.aligned.m16n8k8.row.col.f32.tf32.tf32.f32 "
        "{%0,%1,%2,%3}, {%4,%5,%6,%7}, {%8,%9}, {%0,%1,%2,%3};\n"
        : "+f"(d[0]), "+f"(d[1]), "+f"(d[2]), "+f"(d[3])
        : "r"(a[0]), "r"(a[1]), "r"(a[2]), "r"(a[3]),
          "r"(b[0]), "r"(b[1]));
}

// Swizzled k-major tile storage: flat [row*16 + pos],
// pos(k,row) = (((k&3) + (row>>1)) & 3)*4 + (k>>2)
// Store side: thread holds float4 = k {4q..4q+3} for one row:
//   element j (k=4q+j) goes to group (j + (row>>1))&3, offset q.
__device__ __forceinline__ void store_tile_swz(unsigned* S, int row, int q, float4 v) {
    const int h = (row >> 1) & 3;
    unsigned* base = S + row * 16 + q;
    base[(((0 + h) & 3) << 2)] = f2tf32(v.x);
    base[(((1 + h) & 3) << 2)] = f2tf32(v.y);
    base[(((2 + h) & 3) << 2)] = f2tf32(v.z);
    base[(((3 + h) & 3) << 2)] = f2tf32(v.w);
}

// Fragment load: one LDS.128 yields k = {c, c+4, c+8, c+12} for this row.
__device__ __forceinline__ uint4 ld_frag_swz(const unsigned* S, int row, int c) {
    const int g = (c + (row >> 1)) & 3;
    return *(const uint4*)(S + row * 16 + (g << 2));
}

// ------------------------------------------------------------------
// NN: C[m,n] = sum_k A[m,k]*B[k,n] (+ bias[n]); batched via blockIdx.z
// ------------------------------------------------------------------
__global__ void __launch_bounds__(256, 2) mma_nn(
    const float* __restrict__ A, int lda, long long strideA,
    const float* __restrict__ B, int ldb, long long strideB,
    const float* __restrict__ bias,
    float* __restrict__ C, int ldc, long long strideC,
    int K)
{
    __shared__ unsigned As[BM * BK];       // swizzled
    __shared__ unsigned Bs[BK][BN + 4];    // natural [k][n]

    const int b = blockIdx.z;
    A += (size_t)b * strideA;
    B += (size_t)b * strideB;
    C += (size_t)b * strideC;

    const int tid  = threadIdx.x;
    const int lane = tid & 31;
    const int wid  = tid >> 5;
    const int wm = wid & 3;                // 0..3 -> m
    const int wn = wid >> 2;               // 0..1 -> n
    const int m0 = blockIdx.y * BM;
    const int n0 = blockIdx.x * BN;
    const int c  = lane & 3;
    const int g4 = lane >> 2;

    // A global load mapping: row = tid>>2 (and +64), q = tid&3
    const int ar = tid >> 2, aq = tid & 3;
    // B global load mapping: k = tid>>5 (and +8), 4n = (tid&31)*4
    const int bk = tid >> 5, bn4 = (tid & 31) << 2;

    const float* Ap = A + (size_t)(m0 + ar) * lda + 4 * aq;
    const float* Bp = B + (size_t)bk * ldb + n0 + bn4;

    float acc[2][8][4];
    #pragma unroll
    for (int i = 0; i < 2; i++)
        #pragma unroll
        for (int j = 0; j < 8; j++)
            #pragma unroll
            for (int q = 0; q < 4; q++) acc[i][j][q] = 0.f;

    float4 pa0 = *(const float4*)Ap;
    float4 pa1 = *(const float4*)(Ap + (size_t)64 * lda);
    float4 pb0 = *(const float4*)Bp;
    float4 pb1 = *(const float4*)(Bp + (size_t)8 * ldb);

    const int niter = K / BK;
    for (int kt = 0; kt < niter; kt++) {
        store_tile_swz(As, ar,      aq, pa0);
        store_tile_swz(As, ar + 64, aq, pa1);
        {
            unsigned* p0 = &Bs[bk][bn4];
            p0[0] = f2tf32(pb0.x); p0[1] = f2tf32(pb0.y);
            p0[2] = f2tf32(pb0.z); p0[3] = f2tf32(pb0.w);
            unsigned* p1 = &Bs[bk + 8][bn4];
            p1[0] = f2tf32(pb1.x); p1[1] = f2tf32(pb1.y);
            p1[2] = f2tf32(pb1.z); p1[3] = f2tf32(pb1.w);
        }
        __syncthreads();

        if (kt + 1 < niter) {
            const float* An = Ap + (kt + 1) * BK;
            pa0 = *(const float4*)An;
            pa1 = *(const float4*)(An + (size_t)64 * lda);
            const float* Bn = Bp + (size_t)(kt + 1) * BK * ldb;
            pb0 = *(const float4*)Bn;
            pb1 = *(const float4*)(Bn + (size_t)8 * ldb);
        }

        unsigned af[2][2][4];
        #pragma unroll
        for (int mt = 0; mt < 2; mt++) {
            const int r = wm * 32 + mt * 16 + g4;
            uint4 lo = ld_frag_swz(As, r,     c);
            uint4 hi = ld_frag_swz(As, r + 8, c);
            af[mt][0][0] = lo.x; af[mt][0][1] = hi.x;
            af[mt][0][2] = lo.y; af[mt][0][3] = hi.y;
            af[mt][1][0] = lo.z; af[mt][1][1] = hi.z;
            af[mt][1][2] = lo.w; af[mt][1][3] = hi.w;
        }

        #pragma unroll
        for (int nt = 0; nt < 8; nt++) {
            const int col = wn * 64 + nt * 8 + g4;
            unsigned b0[2] = { Bs[c][col],     Bs[c + 4][col]  };
            unsigned b1[2] = { Bs[c + 8][col], Bs[c + 12][col] };
            #pragma unroll
            for (int mt = 0; mt < 2; mt++) {
                mma_tf32(acc[mt][nt], af[mt][0], b0);
                mma_tf32(acc[mt][nt], af[mt][1], b1);
            }
        }
        __syncthreads();
    }

    #pragma unroll
    for (int mt = 0; mt < 2; mt++) {
        const int r0 = m0 + wm * 32 + mt * 16 + g4;
        #pragma unroll
        for (int nt = 0; nt < 8; nt++) {
            const int col = n0 + wn * 64 + nt * 8 + 2 * c;
            float bx = 0.f, by = 0.f;
            if (bias) { bx = bias[col]; by = bias[col + 1]; }
            float2 v0 = make_float2(acc[mt][nt][0] + bx, acc[mt][nt][1] + by);
            float2 v1 = make_float2(acc[mt][nt][2] + bx, acc[mt][nt][3] + by);
            *(float2*)(C + (size_t)r0 * ldc + col) = v0;
            *(float2*)(C + (size_t)(r0 + 8) * ldc + col) = v1;
        }
    }
}

// ------------------------------------------------------------------
// NT with masked-score epilogue:
// S[m,n] = valid(m,n) ? scale * sum_d A[m,d]*B[n,d] : -10000
// ------------------------------------------------------------------
__global__ void __launch_bounds__(256, 2) mma_nt_mask(
    const float* __restrict__ A, int lda, long long strideA,
    const float* __restrict__ B, int ldb, long long strideB,
    const float* __restrict__ mask,   // [BATCH, SEQ]
    float scale,
    float* __restrict__ C, int ldc, long long strideC,
    int K)
{
    __shared__ unsigned As[BM * BK];    // swizzled
    __shared__ unsigned Bs[BN * BK];    // swizzled (B is k-major per row n)

    const int b = blockIdx.z;
    A += (size_t)b * strideA;
    B += (size_t)b * strideB;
    C += (size_t)b * strideC;
    const float* mrow = mask + (size_t)b * SEQ;

    const int tid  = threadIdx.x;
    const int lane = tid & 31;
    const int wid  = tid >> 5;
    const int wm = wid & 3;
    const int wn = wid >> 2;
    const int m0 = blockIdx.y * BM;
    const int n0 = blockIdx.x * BN;
    const int c  = lane & 3;
    const int g4 = lane >> 2;

    const int ar = tid >> 2, aq = tid & 3;

    const float* Ap = A + (size_t)(m0 + ar) * lda + 4 * aq;
    const float* Bp = B + (size_t)(n0 + ar) * ldb + 4 * aq;

    float acc[2][8][4];
    #pragma unroll
    for (int i = 0; i < 2; i++)
        #pragma unroll
        for (int j = 0; j < 8; j++)
            #pragma unroll
            for (int q = 0; q < 4; q++) acc[i][j][q] = 0.f;

    float4 pa0 = *(const float4*)Ap;
    float4 pa1 = *(const float4*)(Ap + (size_t)64 * lda);
    float4 pb0 = *(const float4*)Bp;
    float4 pb1 = *(const float4*)(Bp + (size_t)64 * ldb);

    const int niter = K / BK;
    for (int kt = 0; kt < niter; kt++) {
        store_tile_swz(As, ar,      aq, pa0);
        store_tile_swz(As, ar + 64, aq, pa1);
        store_tile_swz(Bs, ar,      aq, pb0);
        store_tile_swz(Bs, ar + 64, aq, pb1);
        __syncthreads();

        if (kt + 1 < niter) {
            const float* An = Ap + (kt + 1) * BK;
            pa0 = *(const float4*)An;
            pa1 = *(const float4*)(An + (size_t)64 * lda);
            const float* Bn = Bp + (kt + 1) * BK;
            pb0 = *(const float4*)Bn;
            pb1 = *(const float4*)(Bn + (size_t)64 * ldb);
        }

        unsigned af[2][2][4];
        #pragma unroll
        for (int mt = 0; mt < 2; mt++) {
            const int r = wm * 32 + mt * 16 + g4;
            uint4 lo = ld_frag_swz(As, r,     c);
            uint4 hi = ld_frag_swz(As, r + 8, c);
            af[mt][0][0] = lo.x; af[mt][0][1] = hi.x;
            af[mt][0][2] = lo.y; af[mt][0][3] = hi.y;
            af[mt][1][0] = lo.z; af[mt][1][1] = hi.z;
            af[mt][1][2] = lo.w; af[mt][1][3] = hi.w;
        }

        #pragma unroll
        for (int nt = 0; nt < 8; nt++) {
            uint4 bv = ld_frag_swz(Bs, wn * 64 + nt * 8 + g4, c);
            unsigned b0[2] = { bv.x, bv.y };
            unsigned b1[2] = { bv.z, bv.w };
            #pragma unroll
            for (int mt = 0; mt < 2; mt++) {
                mma_tf32(acc[mt][nt], af[mt][0], b0);
                mma_tf32(acc[mt][nt], af[mt][1], b1);
            }
        }
        __syncthreads();
    }

    #pragma unroll
    for (int mt = 0; mt < 2; mt++) {
        const int r0 = m0 + wm * 32 + mt * 16 + g4;
        const float mr0 = mrow[r0];
        const float mr1 = mrow[r0 + 8];
        #pragma unroll
        for (int nt = 0; nt < 8; nt++) {
            const int col = n0 + wn * 64 + nt * 8 + 2 * c;
            const float mn0 = mrow[col];
            const float mn1 = mrow[col + 1];
            float2 v0, v1;
            v0.x = (mr0 != 0.f && mn0 != 0.f) ? acc[mt][nt][0] * scale : -10000.f;
            v0.y = (mr0 != 0.f && mn1 != 0.f) ? acc[mt][nt][1] * scale : -10000.f;
            v1.x = (mr1 != 0.f && mn0 != 0.f) ? acc[mt][nt][2] * scale : -10000.f;
            v1.y = (mr1 != 0.f && mn1 != 0.f) ? acc[mt][nt][3] * scale : -10000.f;
            *(float2*)(C + (size_t)r0 * ldc + col) = v0;
            *(float2*)(C + (size_t)(r0 + 8) * ldc + col) = v1;
        }
    }
}

// ------------------------------------------------------------------
// Row softmax over N=1024 (in place), one block per row, 256 threads.
// ------------------------------------------------------------------
__global__ void __launch_bounds__(256) softmax_rows(float* __restrict__ S)
{
    const long long row = blockIdx.x;
    float* p = S + row * (long long)SEQ;
    const int tid = threadIdx.x;

    __shared__ float red[256];

    float lmax = -INFINITY;
    #pragma unroll
    for (int i = tid; i < SEQ; i += 256) lmax = fmaxf(lmax, p[i]);
    red[tid] = lmax;
    __syncthreads();
    for (int s = 128; s > 0; s >>= 1) {
        if (tid < s) red[tid] = fmaxf(red[tid], red[tid + s]);
        __syncthreads();
    }
    const float rmax = red[0];
    __syncthreads();

    float lsum = 0.f;
    #pragma unroll
    for (int i = tid; i < SEQ; i += 256) {
        float e = __expf(p[i] - rmax);
        p[i] = e;
        lsum += e;
    }
    red[tid] = lsum;
    __syncthreads();
    for (int s = 128; s > 0; s >>= 1) {
        if (tid < s) red[tid] += red[tid + s];
        __syncthreads();
    }
    const float inv = 1.0f / red[0];
    __syncthreads();

    #pragma unroll
    for (int i = tid; i < SEQ; i += 256) p[i] *= inv;
}

// ------------------------------------------------------------------
// Launch
// ------------------------------------------------------------------
extern "C" void kernel_launch(void* const* d_in, const int* in_sizes, int n_in,
                              void* d_out, int out_size)
{
    (void)in_sizes; (void)n_in; (void)out_size;

    const float* layout_x = (const float*)d_in[0];
    const float* text_x   = (const float*)d_in[1];
    const float* mask     = (const float*)d_in[2];
    const float* Wqkv     = (const float*)d_in[3];
    const float* bqkv     = (const float*)d_in[4];
    const float* Wq       = (const float*)d_in[5];
    const float* bq       = (const float*)d_in[6];
    const float* Wkv      = (const float*)d_in[7];
    const float* bkv      = (const float*)d_in[8];
    const float* Wffn     = (const float*)d_in[9];
    const float* bffn     = (const float*)d_in[10];
    float* out = (float*)d_out;

    float *qkv, *scores, *lo, *cq, *kv, *merge;
    cudaGetSymbolAddress((void**)&qkv,    g_qkv);
    cudaGetSymbolAddress((void**)&scores, g_scores);
    cudaGetSymbolAddress((void**)&lo,     g_lo);
    cudaGetSymbolAddress((void**)&cq,     g_cq);
    cudaGetSymbolAddress((void**)&kv,     g_kv);
    cudaGetSymbolAddress((void**)&merge,  g_merge);

    const float scale = rsqrtf((float)CH);
    const dim3 blk(256);
    const long long sQKV = (long long)SEQ * 3 * CH;
    const long long sS   = (long long)SEQ * SEQ;
    const long long sC   = (long long)SEQ * CH;
    const long long sKV  = (long long)SEQ * 2 * CH;

    // 1) qkv = layout_x @ Wqkv + bqkv   [8192 x 2304 x 768]
    mma_nn<<<dim3(3 * CH / BN, BATCH * SEQ / BM, 1), blk>>>(
        layout_x, CH, 0, Wqkv, 3 * CH, 0, bqkv, qkv, 3 * CH, 0, CH);

    // 2) scores = mask(Q @ K^T * scale)   per-batch [1024 x 1024 x 768]
    mma_nt_mask<<<dim3(SEQ / BN, SEQ / BM, BATCH), blk>>>(
        qkv + 0, 3 * CH, sQKV, qkv + CH, 3 * CH, sQKV, mask, scale,
        scores, SEQ, sS, CH);

    // 3) softmax rows
    softmax_rows<<<BATCH * SEQ, blk>>>(scores);

    // 4) layout_o = P @ V   per-batch [1024 x 768 x 1024]
    mma_nn<<<dim3(CH / BN, SEQ / BM, BATCH), blk>>>(
        scores, SEQ, sS, qkv + 2 * CH, 3 * CH, sQKV, nullptr,
        lo, CH, sC, SEQ);

    // 5) cq = layout_o @ Wq + bq   [8192 x 768 x 768]
    mma_nn<<<dim3(CH / BN, BATCH * SEQ / BM, 1), blk>>>(
        lo, CH, 0, Wq, CH, 0, bq, cq, CH, 0, CH);

    // 6) kv = text_x @ Wkv + bkv   [8192 x 1536 x 768]
    mma_nn<<<dim3(2 * CH / BN, BATCH * SEQ / BM, 1), blk>>>(
        text_x, CH, 0, Wkv, 2 * CH, 0, bkv, kv, 2 * CH, 0, CH);

    // 7) scores = mask(CQ @ CK^T * scale)   per-batch
    mma_nt_mask<<<dim3(SEQ / BN, SEQ / BM, BATCH), blk>>>(
        cq, CH, sC, kv + 0, 2 * CH, sKV, mask, scale,
        scores, SEQ, sS, CH);

    // 8) softmax rows
    softmax_rows<<<BATCH * SEQ, blk>>>(scores);

    // 9) merge = P @ CV   per-batch [1024 x 768 x 1024]
    mma_nn<<<dim3(CH / BN, SEQ / BM, BATCH), blk>>>(
        scores, SEQ, sS, kv + CH, 2 * CH, sKV, nullptr,
        merge, CH, sC, SEQ);

    // 10) out = merge @ Wffn + bffn   [8192 x 768 x 768]
    mma_nn<<<dim3(CH / BN, BATCH * SEQ / BM, 1), blk>>>(
        merge, CH, 0, Wffn, CH, 0, bffn, out, CH, 0, CH);
}